// round 9
// baseline (speedup 1.0000x reference)
#include <cuda_runtime.h>
#include <cuda_bf16.h>

#define TAGS 128
typedef __nv_bfloat162 bf2;

__global__ void __launch_bounds__(TAGS, 1) crf_logz_kernel(
    const float* __restrict__ emissions,     // [B, T, 1, TAGS]
    const int*   __restrict__ token_sizes,   // [B]
    const float* __restrict__ transitions,   // [1, 1, TAGS, TAGS]
    const float* __restrict__ head_t,        // [1, 1, TAGS]
    const float* __restrict__ last_t,        // [1, 1, TAGS]
    float*       __restrict__ out,           // [B, 1]
    int T)
{
    __shared__ __align__(16) __nv_bfloat16 pbuf[2][TAGS];
    __shared__ float wsum[4];

    const int n   = threadIdx.x;    // output tag owned by this thread
    const int wid = n >> 5;         // warp id 0..3
    const int b   = blockIdx.x;     // batch element owned by this CTA
    const int len = token_sizes[b];
    const int Tm1 = T - 1;
    const float* emb = emissions + (size_t)b * T * TAGS;

    // Per-warp rotated chunk walk: warp w processes the 16 p-chunks in block
    // order (blk + w) mod 4 (4 chunks per block). Concurrent warps touch
    // DISJOINT 64B regions -> disjoint smem banks -> no crossbar pileup.
    // Block byte offsets, precomputed (1 block = 4 x uint4 = 64B).
    int boff[4];
#pragma unroll
    for (int k = 0; k < 4; ++k)
        boff[k] = ((k + wid) & 3) * 64;

    // exp(transitions), loaded ALREADY IN THE WARP'S ROTATED ORDER so all
    // T2 indexing inside the step is compile-time constant.
    // Position k (0..15) maps to chunk c = ((k>>2 + wid)&3)*4 + (k&3);
    // chunk c covers m in [8c, 8c+8) -> 4 bf16x2 pairs.
    bf2 T2[TAGS / 2];
#pragma unroll
    for (int k = 0; k < 16; ++k) {
        int c = ((((k >> 2) + wid) & 3) << 2) | (k & 3);
#pragma unroll
        for (int j = 0; j < 4; ++j) {
            int m = c * 8 + 2 * j;
            T2[4 * k + j] = __floats2bfloat162_rn(
                __expf(transitions[(m    ) * TAGS + n]),
                __expf(transitions[(m + 1) * TAGS + n]));
        }
    }

    // alpha_0 = head + emissions[0]  ->  p = exp(alpha)  (bf16 storage)
    pbuf[0][n] = __float2bfloat16(__expf(head_t[n] + emb[n]));
    int etot = 0;        // exact integer sum of stripped binary exponents
    int fb = 0;          // live buffer for the tail bookkeeping

// One recurrence step, compile-time SRC/DST (static smem addressing).
// 64 HFMA2 (rt=2) = 128 cyc fma pacing; 4 accumulators keep dep chains
// issue-balanced. Chunk walk is warp-rotated (boff) for bank disjointness.
// p[0]'s exponent comes from a scalar broadcast LDS consumed only at the
// step tail (off the critical path).
#define STEP(SRC, DST, EV) do {                                            \
    __syncthreads();                                                       \
    unsigned short _cb = __bfloat16_as_ushort(pbuf[SRC][0]);               \
    int _e = (int)((_cb >> 7) & 255) - 127;                                \
    float _sc = __int_as_float((127 - _e) << 23);                          \
    bf2 _Es = __float2bfloat162_rn((EV) * _sc);                            \
    const char* _bp = (const char*)&pbuf[SRC][0];                          \
    bf2 _h0 = __float2bfloat162_rn(0.0f);                                  \
    bf2 _h1 = _h0, _h2 = _h0, _h3 = _h0;                                   \
    _Pragma("unroll")                                                      \
    for (int _kb = 0; _kb < 4; ++_kb) {                                    \
        const uint4* _pq = (const uint4*)(_bp + boff[_kb]);                \
        _Pragma("unroll")                                                  \
        for (int _i = 0; _i < 4; ++_i) {                                   \
            uint4 _q = _pq[_i];                    /* 8 p-halves */        \
            const int _k = _kb * 4 + _i;                                   \
            _h0 = __hfma2(*reinterpret_cast<bf2*>(&_q.x), T2[4*_k    ], _h0);\
            _h1 = __hfma2(*reinterpret_cast<bf2*>(&_q.y), T2[4*_k + 1], _h1);\
            _h2 = __hfma2(*reinterpret_cast<bf2*>(&_q.z), T2[4*_k + 2], _h2);\
            _h3 = __hfma2(*reinterpret_cast<bf2*>(&_q.w), T2[4*_k + 3], _h3);\
        }                                                                  \
    }                                                                      \
    bf2 _s = __hadd2(__hadd2(_h0, _h1), __hadd2(_h2, _h3));                \
    bf2 _t = __hadd2(_s, __lowhigh2highlow(_s));   /* lo+hi in both */     \
    bf2 _pn = __hmul2(_t, _Es);                                            \
    pbuf[DST][n] = __low2bfloat16(_pn);                                    \
    etot += _e;                                                            \
} while (0)

    // Two-stage emission prefetch:
    //   LDG distance 8 steps (interleaved, one load per STEP slot)
    //   __expf applied mid-group, >=4 steps ahead of use.
    int t = 1;
    float E0 = __expf(emb[min(1, Tm1) * TAGS + n]);     // steps t..t+3
    float E1 = __expf(emb[min(2, Tm1) * TAGS + n]);
    float E2 = __expf(emb[min(3, Tm1) * TAGS + n]);
    float E3 = __expf(emb[min(4, Tm1) * TAGS + n]);
    float Q0 = emb[min(5, Tm1) * TAGS + n];             // raw, steps t+4..t+7
    float Q1 = emb[min(6, Tm1) * TAGS + n];
    float Q2 = emb[min(7, Tm1) * TAGS + n];
    float Q3 = emb[min(8, Tm1) * TAGS + n];

    // Fast loop: t+12 <= len implies prefetch rows t+8..t+11 < T: no clamps.
    for (; t + 12 <= len; t += 4) {
        const float* ep = emb + (size_t)(t + 8) * TAGS + n;
        float R0 = ep[0];
        STEP(0, 1, E0);
        float R1 = ep[TAGS];
        STEP(1, 0, E1);
        float R2 = ep[2 * TAGS];
        E0 = __expf(Q0); E1 = __expf(Q1);   // loaded a full group ago
        E2 = __expf(Q2); E3 = __expf(Q3);
        STEP(0, 1, E2);
        float R3 = ep[3 * TAGS];
        STEP(1, 0, E3);
        Q0 = R0; Q1 = R1; Q2 = R2; Q3 = R3;
    }
    // Clamped boundary loop (<= 2 iterations).
    for (; t + 4 <= len; t += 4) {
        int tp = t + 8;
        float R0 = emb[min(tp,     Tm1) * TAGS + n];
        STEP(0, 1, E0);
        float R1 = emb[min(tp + 1, Tm1) * TAGS + n];
        STEP(1, 0, E1);
        float R2 = emb[min(tp + 2, Tm1) * TAGS + n];
        E0 = __expf(Q0); E1 = __expf(Q1);
        E2 = __expf(Q2); E3 = __expf(Q3);
        STEP(0, 1, E2);
        float R3 = emb[min(tp + 3, Tm1) * TAGS + n];
        STEP(1, 0, E3);
        Q0 = R0; Q1 = R1; Q2 = R2; Q3 = R3;
    }
    // Tail (0-3 steps); E0..E2 already exp()'d.
    if (t < len) { STEP(0, 1, E0); fb = 1; ++t; }
    if (t < len) { STEP(1, 0, E1); fb = 0; ++t; }
    if (t < len) { STEP(0, 1, E2); fb = 1; ++t; }

    // Finalize: out[b] = etot*ln2 + log( sum_n p[n] * exp(last[n]) )  (fp32)
    __syncthreads();
    float v = __bfloat162float(pbuf[fb][n]) * __expf(last_t[n]);
#pragma unroll
    for (int sft = 16; sft > 0; sft >>= 1)
        v += __shfl_xor_sync(0xffffffffu, v, sft);
    if ((n & 31) == 0) wsum[n >> 5] = v;
    __syncthreads();
    if (n == 0)
        out[b] = (float)((double)etot * 0.6931471805599453 +
                         (double)__logf(wsum[0] + wsum[1] + wsum[2] + wsum[3]));
}

extern "C" void kernel_launch(void* const* d_in, const int* in_sizes, int n_in,
                              void* d_out, int out_size) {
    const float* em = (const float*)d_in[0];
    const int*   ts = (const int*)  d_in[1];
    const float* tr = (const float*)d_in[2];
    const float* hd = (const float*)d_in[3];
    const float* lt = (const float*)d_in[4];
    float* out = (float*)d_out;

    int B = in_sizes[1];                       // token_sizes count
    int T = in_sizes[0] / (B * TAGS);          // C == 1

    crf_logz_kernel<<<B, TAGS>>>(em, ts, tr, hd, lt, out, T);
}

// round 10
// speedup vs baseline: 1.0717x; 1.0717x over previous
#include <cuda_runtime.h>
#include <cuda_bf16.h>

#define TAGS 128
typedef __nv_bfloat162 bf2;

__global__ void __launch_bounds__(TAGS, 1) crf_logz_kernel(
    const float* __restrict__ emissions,     // [B, T, 1, TAGS]
    const int*   __restrict__ token_sizes,   // [B]
    const float* __restrict__ transitions,   // [1, 1, TAGS, TAGS]
    const float* __restrict__ head_t,        // [1, 1, TAGS]
    const float* __restrict__ last_t,        // [1, 1, TAGS]
    float*       __restrict__ out,           // [B, 1]
    int T)
{
    __shared__ __align__(16) __nv_bfloat16 pbuf[2][TAGS];
    __shared__ float wsum[4];

    const int n = threadIdx.x;      // output tag owned by this thread
    const int b = blockIdx.x;       // batch element owned by this CTA
    const int len = token_sizes[b];
    const int Tm1 = T - 1;
    const float* emb = emissions + (size_t)b * T * TAGS;

    // exp(transitions) column n as bf16x2 pairs: T2[i] = (T[2i,n], T[2i+1,n]).
    bf2 T2[TAGS / 2];
#pragma unroll
    for (int i = 0; i < TAGS / 2; ++i)
        T2[i] = __floats2bfloat162_rn(__expf(transitions[(2 * i    ) * TAGS + n]),
                                      __expf(transitions[(2 * i + 1) * TAGS + n]));

    // alpha_0 = head + emissions[0]  ->  p = exp(alpha)  (bf16 storage)
    pbuf[0][n] = __float2bfloat16(__expf(head_t[n] + emb[n]));
    int etot = 0;        // exact integer sum of stripped binary exponents
    int fb = 0;          // live buffer for the tail bookkeeping

// One recurrence step, compile-time SRC/DST (static smem addressing).
// 64 HFMA2 (rt=2) = 128 cyc fma pacing. TWO accumulators: reissue spacing
// per acc = 2 instr = 4 cyc = exactly HFMA2 lat (stall-free; the binding
// hazard is the LDS operand either way) and the reduce tree is one level
// shorter. Scale applied BEFORE the lo/hi fold so the hmul2 overlaps the
// swap PRMT. p[0]'s exponent comes from the first matvec load (_q0.x).
#define STEP(SRC, DST, EV) do {                                            \
    __syncthreads();                                                       \
    const uint4* _pd = reinterpret_cast<const uint4*>(&pbuf[SRC][0]);      \
    uint4 _q0 = _pd[0];                                                    \
    int _e = (int)((_q0.x >> 7) & 255) - 127;      /* bf16 exp of p[0] */  \
    float _sc = __int_as_float((127 - _e) << 23);                          \
    bf2 _Es = __float2bfloat162_rn((EV) * _sc);                            \
    bf2 _h0 = __float2bfloat162_rn(0.0f);                                  \
    bf2 _h1 = _h0;                                                         \
    _h0 = __hfma2(*reinterpret_cast<bf2*>(&_q0.x), T2[0], _h0);            \
    _h1 = __hfma2(*reinterpret_cast<bf2*>(&_q0.y), T2[1], _h1);            \
    _h0 = __hfma2(*reinterpret_cast<bf2*>(&_q0.z), T2[2], _h0);            \
    _h1 = __hfma2(*reinterpret_cast<bf2*>(&_q0.w), T2[3], _h1);            \
    _Pragma("unroll")                                                      \
    for (int _i = 1; _i < 16; ++_i) {                                      \
        uint4 _q = _pd[_i];                        /* 8 p-halves */        \
        _h0 = __hfma2(*reinterpret_cast<bf2*>(&_q.x), T2[4 * _i    ], _h0);\
        _h1 = __hfma2(*reinterpret_cast<bf2*>(&_q.y), T2[4 * _i + 1], _h1);\
        _h0 = __hfma2(*reinterpret_cast<bf2*>(&_q.z), T2[4 * _i + 2], _h0);\
        _h1 = __hfma2(*reinterpret_cast<bf2*>(&_q.w), T2[4 * _i + 3], _h1);\
    }                                                                      \
    bf2 _s = __hadd2(_h0, _h1);                                            \
    bf2 _v = __hmul2(_s, _Es);                     /* scale both lanes */  \
    bf2 _pn = __hadd2(_v, __lowhigh2highlow(_v));  /* lo+hi fold */        \
    pbuf[DST][n] = __low2bfloat16(_pn);                                    \
    etot += _e;                                                            \
} while (0)

    // Two-stage emission prefetch:
    //   LDG distance 8 steps (interleaved, one load per STEP slot)
    //   __expf applied mid-group, >=4 steps ahead of use.
    int t = 1;
    float E0 = __expf(emb[min(1, Tm1) * TAGS + n]);     // steps t..t+3
    float E1 = __expf(emb[min(2, Tm1) * TAGS + n]);
    float E2 = __expf(emb[min(3, Tm1) * TAGS + n]);
    float E3 = __expf(emb[min(4, Tm1) * TAGS + n]);
    float Q0 = emb[min(5, Tm1) * TAGS + n];             // raw, steps t+4..t+7
    float Q1 = emb[min(6, Tm1) * TAGS + n];
    float Q2 = emb[min(7, Tm1) * TAGS + n];
    float Q3 = emb[min(8, Tm1) * TAGS + n];

    // Fast loop: t+12 <= len implies prefetch rows t+8..t+11 < T: no clamps.
    for (; t + 12 <= len; t += 4) {
        const float* ep = emb + (size_t)(t + 8) * TAGS + n;
        float R0 = ep[0];
        STEP(0, 1, E0);
        float R1 = ep[TAGS];
        STEP(1, 0, E1);
        float R2 = ep[2 * TAGS];
        E0 = __expf(Q0); E1 = __expf(Q1);   // loaded a full group ago
        E2 = __expf(Q2); E3 = __expf(Q3);
        STEP(0, 1, E2);
        float R3 = ep[3 * TAGS];
        STEP(1, 0, E3);
        Q0 = R0; Q1 = R1; Q2 = R2; Q3 = R3;
    }
    // Clamped boundary loop (<= 2 iterations).
    for (; t + 4 <= len; t += 4) {
        int tp = t + 8;
        float R0 = emb[min(tp,     Tm1) * TAGS + n];
        STEP(0, 1, E0);
        float R1 = emb[min(tp + 1, Tm1) * TAGS + n];
        STEP(1, 0, E1);
        float R2 = emb[min(tp + 2, Tm1) * TAGS + n];
        E0 = __expf(Q0); E1 = __expf(Q1);
        E2 = __expf(Q2); E3 = __expf(Q3);
        STEP(0, 1, E2);
        float R3 = emb[min(tp + 3, Tm1) * TAGS + n];
        STEP(1, 0, E3);
        Q0 = R0; Q1 = R1; Q2 = R2; Q3 = R3;
    }
    // Tail (0-3 steps); E0..E2 already exp()'d.
    if (t < len) { STEP(0, 1, E0); fb = 1; ++t; }
    if (t < len) { STEP(1, 0, E1); fb = 0; ++t; }
    if (t < len) { STEP(0, 1, E2); fb = 1; ++t; }

    // Finalize: out[b] = etot*ln2 + log( sum_n p[n] * exp(last[n]) )  (fp32)
    __syncthreads();
    float v = __bfloat162float(pbuf[fb][n]) * __expf(last_t[n]);
#pragma unroll
    for (int sft = 16; sft > 0; sft >>= 1)
        v += __shfl_xor_sync(0xffffffffu, v, sft);
    if ((n & 31) == 0) wsum[n >> 5] = v;
    __syncthreads();
    if (n == 0)
        out[b] = (float)((double)etot * 0.6931471805599453 +
                         (double)__logf(wsum[0] + wsum[1] + wsum[2] + wsum[3]));
}

extern "C" void kernel_launch(void* const* d_in, const int* in_sizes, int n_in,
                              void* d_out, int out_size) {
    const float* em = (const float*)d_in[0];
    const int*   ts = (const int*)  d_in[1];
    const float* tr = (const float*)d_in[2];
    const float* hd = (const float*)d_in[3];
    const float* lt = (const float*)d_in[4];
    float* out = (float*)d_out;

    int B = in_sizes[1];                       // token_sizes count
    int T = in_sizes[0] / (B * TAGS);          // C == 1

    crf_logz_kernel<<<B, TAGS>>>(em, ts, tr, hd, lt, out, T);
}